// round 7
// baseline (speedup 1.0000x reference)
#include <cuda_runtime.h>
#include <math.h>

#define B_   16
#define CIN1 256
#define COUT 128
#define H_   128
#define W_   128

// Scratch (device globals; no allocation).
__device__ float g_up  [(size_t)B_ * COUT * H_ * W_];
__device__ float g_down[(size_t)B_ * COUT * H_ * W_];
__device__ float g_xtf [(size_t)B_ * CIN1 * H_ * W_];   // tf32-rounded x
__device__ float g_wup [9 * CIN1 * COUT];               // packed [tap][ci][co]
__device__ float g_wdn [9 * CIN1 * COUT];
__device__ float g_wp  [9 * COUT * COUT];

__device__ __forceinline__ unsigned f2tf(float f) {
    unsigned r;
    asm("cvt.rna.tf32.f32 %0, %1;" : "=r"(r) : "f"(f));
    return r;
}

__device__ __forceinline__ void mma_tf32(float* c, const unsigned* a, unsigned b0, unsigned b1) {
    asm volatile(
        "mma.sync.aligned.m16n8k8.row.col.f32.tf32.tf32.f32 "
        "{%0,%1,%2,%3},{%4,%5,%6,%7},{%8,%9},{%0,%1,%2,%3};"
        : "+f"(c[0]), "+f"(c[1]), "+f"(c[2]), "+f"(c[3])
        : "r"(a[0]), "r"(a[1]), "r"(a[2]), "r"(a[3]), "r"(b0), "r"(b1));
}

__device__ __forceinline__ void cpa16(unsigned* dst, const float* src, bool pred) {
    unsigned d = (unsigned)__cvta_generic_to_shared(dst);
    int sz = pred ? 16 : 0;
    asm volatile("cp.async.ca.shared.global [%0], [%1], 16, %2;"
                 :: "r"(d), "l"(src), "r"(sz));
}

// smem word layout (double buffered):
//   ws[tap][ci][136]  : 9*8*136  = 9792 words per buffer
//   xs[row][ci][136]  : 4*8*136  = 4352 words per buffer
#define WS_W 9792
#define XS_W 4352
#define BUF_W (WS_W + XS_W)
#define SMEM_BYTES (2 * BUF_W * 4)

// ---------------------------------------------------------------------------
// tf32 tensor-core implicit-GEMM 3x3 conv + BN (+ReLU), cp.async pipelined.
// Block = 256 threads, tile M=128 co x N=256 px (2 rows x 128 w).
// ---------------------------------------------------------------------------
template <int CIN, bool RELU>
__global__ __launch_bounds__(256, 1)
void conv3x3_tf32(const float* __restrict__ xtf, const float* __restrict__ wp,
                  const float* __restrict__ gamma, const float* __restrict__ beta,
                  const float* __restrict__ mean, const float* __restrict__ var,
                  float* __restrict__ out)
{
    extern __shared__ unsigned sm[];
    unsigned* wsb[2] = { sm,          sm + BUF_W          };
    unsigned* xsb[2] = { sm + WS_W,   sm + BUF_W + WS_W   };

    const int tid  = threadIdx.x;
    const int b    = blockIdx.y;
    const int r0   = blockIdx.x * 2;

    const int warp = tid >> 5;
    const int lane = tid & 31;
    const int g    = lane >> 2;
    const int tig  = lane & 3;

    const int mwarp  = warp & 1;
    const int nwarp  = warp >> 1;
    const int rloc   = nwarp >> 1;
    const int wn0    = (nwarp & 1) * 64;
    const int cobase = mwarp * 64;

    // static-zero halo columns (col 3 <- gw=-1, col 132 <- gw=128), both buffers
    if (tid < 128) {
        int bufsel = tid & 1;
        int colsel = (tid >> 1) & 1;
        int ci     = (tid >> 2) & 7;
        int row    = (tid >> 5) & 3;
        xsb[bufsel][row * 1088 + ci * 136 + (colsel ? 132 : 3)] = 0u;
    }

    float acc[4][8][4];
#pragma unroll
    for (int mt = 0; mt < 4; mt++)
#pragma unroll
        for (int nt = 0; nt < 8; nt++)
#pragma unroll
            for (int i = 0; i < 4; i++) acc[mt][nt][i] = 0.f;

    constexpr int NC = CIN / 8;

    // ---- staging (all cp.async 16B) ----
    auto stage = [&](int c, int bufsel) {
        const int ci0 = c * 8;
        unsigned* ws = wsb[bufsel];
        unsigned* xs = xsb[bufsel];
        // weights: 9 taps x 8 ci x 128 co  (2304 x 16B)
#pragma unroll
        for (int k = 0; k < 9; k++) {
            int idx = tid + k * 256;
            int tap = idx >> 8;
            int rem = idx & 255;
            int ci  = rem >> 5;
            int cc  = rem & 31;
            cpa16(ws + tap * 1088 + ci * 136 + cc * 4,
                  wp + ((size_t)tap * CIN + ci0 + ci) * COUT + cc * 4, true);
        }
        // x: 4 rows x 8 ci x 128 cols  (1024 x 16B), zero-fill OOB rows
#pragma unroll
        for (int k = 0; k < 4; k++) {
            int idx = tid + k * 256;
            int row = idx >> 8;
            int rem = idx & 255;
            int ci  = rem >> 5;
            int cc  = rem & 31;
            int gh  = r0 - 1 + row;
            bool ok = (gh >= 0) && (gh < H_);
            cpa16(xs + row * 1088 + ci * 136 + 4 + cc * 4,
                  xtf + (((size_t)b * CIN + ci0 + ci) * H_ + (ok ? gh : 0)) * W_ + cc * 4,
                  ok);
        }
    };

    stage(0, 0);
    asm volatile("cp.async.commit_group;");

    for (int c = 0; c < NC; c++) {
        if (c + 1 < NC) {
            stage(c + 1, (c + 1) & 1);
            asm volatile("cp.async.commit_group;");
            asm volatile("cp.async.wait_group 1;");
        } else {
            asm volatile("cp.async.wait_group 0;");
        }
        __syncthreads();

        const unsigned* ws = wsb[c & 1];
        const unsigned* xs = xsb[c & 1];

#pragma unroll
        for (int dh = 0; dh < 3; dh++)
#pragma unroll
            for (int dw = 0; dw < 3; dw++) {
                const int tap = dh * 3 + dw;
                const unsigned* wr0 = ws + tap * 1088 + tig * 136;
                const unsigned* wr1 = wr0 + 4 * 136;
                unsigned a[4][4];
#pragma unroll
                for (int mt = 0; mt < 4; mt++) {
                    int cb = cobase + mt * 16 + g;
                    a[mt][0] = wr0[cb];
                    a[mt][1] = wr0[cb + 8];
                    a[mt][2] = wr1[cb];
                    a[mt][3] = wr1[cb + 8];
                }
                const unsigned* p0 = xs + (rloc + dh) * 1088 + tig * 136
                                        + wn0 + g + dw + 3;
                const unsigned* p1 = p0 + 4 * 136;
#pragma unroll
                for (int nt = 0; nt < 8; nt++) {
                    unsigned b0 = p0[nt * 8];
                    unsigned b1 = p1[nt * 8];
#pragma unroll
                    for (int mt = 0; mt < 4; mt++)
                        mma_tf32(acc[mt][nt], a[mt], b0, b1);
                }
            }
        __syncthreads();   // buffer reuse fence for stage(c+2)
    }

    // ---- epilogue: BN (+ReLU), float2 stores ----
    const int h = r0 + rloc;
#pragma unroll
    for (int mt = 0; mt < 4; mt++) {
        int c0 = cobase + mt * 16 + g;
        int c1 = c0 + 8;
        float inv0 = gamma[c0] * rsqrtf(var[c0] + 1e-5f);
        float bi0  = beta[c0] - mean[c0] * inv0;
        float inv1 = gamma[c1] * rsqrtf(var[c1] + 1e-5f);
        float bi1  = beta[c1] - mean[c1] * inv1;
        float* o0 = out + (((size_t)b * COUT + c0) * H_ + h) * W_;
        float* o1 = out + (((size_t)b * COUT + c1) * H_ + h) * W_;
#pragma unroll
        for (int nt = 0; nt < 8; nt++) {
            int w = wn0 + nt * 8 + tig * 2;
            float v0 = acc[mt][nt][0] * inv0 + bi0;
            float v1 = acc[mt][nt][1] * inv0 + bi0;
            float v2 = acc[mt][nt][2] * inv1 + bi1;
            float v3 = acc[mt][nt][3] * inv1 + bi1;
            if (RELU) {
                v0 = fmaxf(v0, 0.f); v1 = fmaxf(v1, 0.f);
                v2 = fmaxf(v2, 0.f); v3 = fmaxf(v3, 0.f);
            }
            *(float2*)(o0 + w) = make_float2(v0, v1);
            *(float2*)(o1 + w) = make_float2(v2, v3);
        }
    }
}

// ---------------------------------------------------------------------------
// Prep: round x to tf32 bits (vectorized).
// ---------------------------------------------------------------------------
__global__ void round_x(const float* __restrict__ x, float* __restrict__ xt, size_t n4)
{
    size_t i = (size_t)blockIdx.x * blockDim.x + threadIdx.x;
    if (i >= n4) return;
    float4 v = ((const float4*)x)[i];
    v.x = __uint_as_float(f2tf(v.x));
    v.y = __uint_as_float(f2tf(v.y));
    v.z = __uint_as_float(f2tf(v.z));
    v.w = __uint_as_float(f2tf(v.w));
    ((float4*)xt)[i] = v;
}

// Prep: pack weights [co][ci][3][3] -> tf32 [tap][ci][co].
template <int CIN>
__global__ void pack_w(const float* __restrict__ w, float* __restrict__ wp)
{
    int idx = blockIdx.x * blockDim.x + threadIdx.x;   // 9*CIN*COUT
    if (idx >= 9 * CIN * COUT) return;
    int co  = idx & (COUT - 1);
    int r   = idx / COUT;
    int ci  = r % CIN;
    int tap = r / CIN;
    wp[idx] = __uint_as_float(f2tf(w[((size_t)co * CIN + ci) * 9 + tap]));
}

// ---------------------------------------------------------------------------
// TopPool (reverse cummax over H) + add; emits tf32-rounded merge.
// ---------------------------------------------------------------------------
__global__ void toppool_add(const float* __restrict__ up,
                            const float* __restrict__ down,
                            float* __restrict__ merge)
{
    int idx = blockIdx.x * blockDim.x + threadIdx.x;
    if (idx >= B_ * COUT * W_) return;
    int w  = idx % W_;
    int bc = idx / W_;
    const float* u = up   + (size_t)bc * H_ * W_ + w;
    const float* d = down + (size_t)bc * H_ * W_ + w;
    float*       m = merge + (size_t)bc * H_ * W_ + w;
    float run = -INFINITY;
#pragma unroll 4
    for (int h = H_ - 1; h >= 0; h--) {
        run = fmaxf(run, u[(size_t)h * W_]);
        m[(size_t)h * W_] = __uint_as_float(f2tf(run + d[(size_t)h * W_]));
    }
}

// ---------------------------------------------------------------------------
// LeftPool (reverse cummax over W): Hillis-Steele reverse max-scan per row.
// ---------------------------------------------------------------------------
__global__ void leftpool(const float* __restrict__ in, float* __restrict__ out)
{
    __shared__ float s[W_];
    size_t base = (size_t)blockIdx.x * W_;
    int w = threadIdx.x;
    float v = in[base + w];
    s[w] = v;
    __syncthreads();
#pragma unroll
    for (int off = 1; off < W_; off <<= 1) {
        float other = (w + off < W_) ? s[w + off] : -INFINITY;
        __syncthreads();
        v = fmaxf(v, other);
        s[w] = v;
        __syncthreads();
    }
    out[base + w] = v;
}

// ---------------------------------------------------------------------------
extern "C" void kernel_launch(void* const* d_in, const int* in_sizes, int n_in,
                              void* d_out, int out_size)
{
    const float* x      = (const float*)d_in[0];
    const float* w_up   = (const float*)d_in[1];
    const float* up_g   = (const float*)d_in[2];
    const float* up_b   = (const float*)d_in[3];
    const float* up_m   = (const float*)d_in[4];
    const float* up_v   = (const float*)d_in[5];
    const float* w_down = (const float*)d_in[6];
    const float* dn_g   = (const float*)d_in[7];
    const float* dn_b   = (const float*)d_in[8];
    const float* dn_m   = (const float*)d_in[9];
    const float* dn_v   = (const float*)d_in[10];
    const float* w_p    = (const float*)d_in[11];
    const float* p_g    = (const float*)d_in[12];
    const float* p_b    = (const float*)d_in[13];
    const float* p_m    = (const float*)d_in[14];
    const float* p_v    = (const float*)d_in[15];
    float* outp = (float*)d_out;

    float *up_ptr, *down_ptr, *xtf, *wup, *wdn, *wpp;
    cudaGetSymbolAddress((void**)&up_ptr,   g_up);
    cudaGetSymbolAddress((void**)&down_ptr, g_down);
    cudaGetSymbolAddress((void**)&xtf,      g_xtf);
    cudaGetSymbolAddress((void**)&wup,      g_wup);
    cudaGetSymbolAddress((void**)&wdn,      g_wdn);
    cudaGetSymbolAddress((void**)&wpp,      g_wp);

    cudaFuncSetAttribute(conv3x3_tf32<CIN1, true>,
                         cudaFuncAttributeMaxDynamicSharedMemorySize, SMEM_BYTES);
    cudaFuncSetAttribute(conv3x3_tf32<COUT, false>,
                         cudaFuncAttributeMaxDynamicSharedMemorySize, SMEM_BYTES);

    // ---- prep: tf32-round x, pack+round weights ----
    {
        size_t n4 = (size_t)B_ * CIN1 * H_ * W_ / 4;
        round_x<<<(unsigned)((n4 + 255) / 256), 256>>>(x, xtf, n4);
        int nw = 9 * CIN1 * COUT;
        pack_w<CIN1><<<(nw + 255) / 256, 256>>>(w_up,   wup);
        pack_w<CIN1><<<(nw + 255) / 256, 256>>>(w_down, wdn);
        int np = 9 * COUT * COUT;
        pack_w<COUT><<<(np + 255) / 256, 256>>>(w_p, wpp);
    }

    dim3 cgrid(H_ / 2, B_);
    conv3x3_tf32<CIN1, true><<<cgrid, 256, SMEM_BYTES>>>(xtf, wup, up_g, up_b, up_m, up_v, up_ptr);
    conv3x3_tf32<CIN1, true><<<cgrid, 256, SMEM_BYTES>>>(xtf, wdn, dn_g, dn_b, dn_m, dn_v, down_ptr);
    {
        int total = B_ * COUT * W_;
        toppool_add<<<(total + 255) / 256, 256>>>(up_ptr, down_ptr, down_ptr);
    }
    conv3x3_tf32<COUT, false><<<cgrid, 256, SMEM_BYTES>>>(down_ptr, wpp, p_g, p_b, p_m, p_v, up_ptr);
    leftpool<<<B_ * COUT * H_, W_>>>(up_ptr, outp);
}

// round 10
// speedup vs baseline: 1.8147x; 1.8147x over previous
#include <cuda_runtime.h>
#include <cuda_fp16.h>
#include <math.h>

#define B_   16
#define H_   128
#define W_   128
#define CIN1 256
#define COUT 128

// Scratch (device globals; no allocation). All half2 stored as unsigned.
__device__ unsigned g_xh [(size_t)B_ * 128 * H_ * W_];  // x pairs / conv3 fp32 out (134MB)
__device__ unsigned g_uph[(size_t)B_ *  64 * H_ * W_];  // up pairs (67MB)
__device__ unsigned g_dnh[(size_t)B_ *  64 * H_ * W_];  // down/merge pairs
__device__ unsigned g_whu[16 * 9 * 1024];               // packed A: [chunk][tap][ci2][co]
__device__ unsigned g_whd[16 * 9 * 1024];
__device__ unsigned g_whp[ 8 * 9 * 1024];

// ---------------- helpers ----------------
__device__ __forceinline__ void cpa16(unsigned* dst, const unsigned* src, bool ok) {
    unsigned d = (unsigned)__cvta_generic_to_shared(dst);
    int sz = ok ? 16 : 0;
    asm volatile("cp.async.ca.shared.global [%0], [%1], 16, %2;" :: "r"(d), "l"(src), "r"(sz));
}
#define CPCOMMIT() asm volatile("cp.async.commit_group;")
#define CPWAIT(n)  asm volatile("cp.async.wait_group %0;"::"n"(n))

__device__ __forceinline__ void mma_f16(float* c, const unsigned* a, unsigned b0, unsigned b1) {
    asm volatile(
        "mma.sync.aligned.m16n8k16.row.col.f32.f16.f16.f32 "
        "{%0,%1,%2,%3},{%4,%5,%6,%7},{%8,%9},{%0,%1,%2,%3};"
        : "+f"(c[0]), "+f"(c[1]), "+f"(c[2]), "+f"(c[3])
        : "r"(a[0]), "r"(a[1]), "r"(a[2]), "r"(a[3]), "r"(b0), "r"(b1));
}
__device__ __forceinline__ unsigned h2u(float lo, float hi) {
    __half2 h = __floats2half2_rn(lo, hi);
    return *(unsigned*)&h;
}

// smem words (double buffered): ws[tap][ci2][136] = 9792, xs[row][ci2][136] = 4352
#define WS_W 9792
#define XS_W 4352
#define BUF_W (WS_W + XS_W)
#define SMEM_BYTES (2 * BUF_W * 4)

// ---------------------------------------------------------------------------
// fp16 mma.sync implicit-GEMM 3x3 conv + BN (+ReLU), cp.async double-buffered.
// Block=256, tile M=128co x 256px (2 rows x 128w), K streamed 16ci (8 pairs)/chunk.
// ---------------------------------------------------------------------------
template <int NCC, bool RELU, bool OUTH>
__global__ __launch_bounds__(256, 1)
void conv_h(const unsigned* __restrict__ xh, const unsigned* __restrict__ wh,
            const float* __restrict__ gam, const float* __restrict__ bet,
            const float* __restrict__ mu,  const float* __restrict__ var,
            unsigned* __restrict__ outv)
{
    extern __shared__ unsigned sm[];
    unsigned* wsb[2] = { sm,        sm + BUF_W        };
    unsigned* xsb[2] = { sm + WS_W, sm + BUF_W + WS_W };

    const int tid  = threadIdx.x;
    const int b    = blockIdx.y;
    const int h0   = blockIdx.x * 2;

    const int warp = tid >> 5;
    const int lane = tid & 31;
    const int g    = lane >> 2;
    const int tig  = lane & 3;

    const int mwarp  = warp & 1;
    const int nwarp  = warp >> 1;
    const int rloc   = nwarp >> 1;
    const int wn0    = (nwarp & 1) * 64;
    const int cobase = mwarp * 64;

    // static-zero halo cols (3 <- w=-1, 132 <- w=128), both buffers
    if (tid < 128) {
        int bufsel = tid & 1, colsel = (tid >> 1) & 1;
        int ci2 = (tid >> 2) & 7, row = (tid >> 5) & 3;
        xsb[bufsel][row * 1088 + ci2 * 136 + (colsel ? 132 : 3)] = 0u;
    }

    float acc[4][8][4];
#pragma unroll
    for (int mt = 0; mt < 4; mt++)
#pragma unroll
        for (int nt = 0; nt < 8; nt++)
#pragma unroll
            for (int i = 0; i < 4; i++) acc[mt][nt][i] = 0.f;

    auto stage = [&](int c) {
        unsigned* ws = wsb[c & 1];
        unsigned* xs = xsb[c & 1];
        // weights: 9 taps x 8 ci2 x 128 co (2304 x 16B)
#pragma unroll
        for (int k = 0; k < 9; k++) {
            int fi = tid + (k << 8);
            int tap = fi >> 8, rem = fi & 255, ci2 = rem >> 5, cg = rem & 31;
            cpa16(ws + (tap * 8 + ci2) * 136 + cg * 4,
                  wh + (size_t)(c * 9 + tap) * 1024 + ci2 * 128 + cg * 4, true);
        }
        // x: 4 rows x 8 ci2 x 128 half2 (1024 x 16B), zero-fill OOB rows
#pragma unroll
        for (int k = 0; k < 4; k++) {
            int fi = tid + (k << 8);
            int row = fi >> 8, rem = fi & 255, ci2 = rem >> 5, wg = rem & 31;
            int gh = h0 - 1 + row;
            bool ok = (gh >= 0) && (gh < H_);
            cpa16(xs + row * 1088 + ci2 * 136 + 4 + wg * 4,
                  xh + ((size_t)((b * NCC + c) * 8 + ci2) * H_ + (ok ? gh : 0)) * W_ + wg * 4,
                  ok);
        }
    };

    stage(0); CPCOMMIT();
    if (NCC > 1) { stage(1); CPCOMMIT(); }

    for (int c = 0; c < NCC; c++) {
        if (c + 1 < NCC) { CPWAIT(1); } else { CPWAIT(0); }
        __syncthreads();

        const unsigned* ws = wsb[c & 1];
        const unsigned* xs = xsb[c & 1];

#pragma unroll
        for (int dh = 0; dh < 3; dh++)
#pragma unroll
            for (int dw = 0; dw < 3; dw++) {
                const int tap = dh * 3 + dw;
                const unsigned* wr0 = ws + (tap * 8 + tig) * 136;
                const unsigned* wr1 = ws + (tap * 8 + tig + 4) * 136;
                unsigned a[4][4];
#pragma unroll
                for (int mt = 0; mt < 4; mt++) {
                    int cb = cobase + mt * 16 + g;
                    a[mt][0] = wr0[cb];       // (row g,   k=2tig..)
                    a[mt][1] = wr0[cb + 8];   // (row g+8, k=2tig..)
                    a[mt][2] = wr1[cb];       // (row g,   k=8+2tig..)
                    a[mt][3] = wr1[cb + 8];   // (row g+8, k=8+2tig..)
                }
                const unsigned* p0 = xs + (rloc + dh) * 1088 + tig * 136 + wn0 + g + dw + 3;
                const unsigned* p1 = p0 + 4 * 136;
#pragma unroll
                for (int nt = 0; nt < 8; nt++) {
                    unsigned b0 = p0[nt * 8];
                    unsigned b1 = p1[nt * 8];
#pragma unroll
                    for (int mt = 0; mt < 4; mt++)
                        mma_f16(acc[mt][nt], a[mt], b0, b1);
                }
            }
        __syncthreads();   // buffer reuse fence before stage(c+2)
        if (c + 2 < NCC) { stage(c + 2); CPCOMMIT(); }
    }

    // ---- epilogue: BN (+ReLU) ----
    const int h = h0 + rloc;
#pragma unroll
    for (int mt = 0; mt < 4; mt++) {
        int ca = cobase + mt * 16 + g;     // pair lo
        int cb2 = ca + 8;                  // pair hi
        float inva = gam[ca]  * rsqrtf(var[ca]  + 1e-5f);
        float bia  = bet[ca]  - mu[ca]  * inva;
        float invb = gam[cb2] * rsqrtf(var[cb2] + 1e-5f);
        float bib  = bet[cb2] - mu[cb2] * invb;
        if (OUTH) {
            int j = (mwarp * 4 + mt) * 8 + g;   // pair row
            unsigned* rp = outv + ((size_t)(b * 64 + j) * H_ + h) * W_;
#pragma unroll
            for (int nt = 0; nt < 8; nt++) {
                int w0 = wn0 + nt * 8 + 2 * tig;
                float v0 = acc[mt][nt][0] * inva + bia;
                float v1 = acc[mt][nt][1] * inva + bia;
                float v2 = acc[mt][nt][2] * invb + bib;
                float v3 = acc[mt][nt][3] * invb + bib;
                if (RELU) { v0=fmaxf(v0,0.f); v1=fmaxf(v1,0.f); v2=fmaxf(v2,0.f); v3=fmaxf(v3,0.f); }
                uint2 q; q.x = h2u(v0, v2); q.y = h2u(v1, v3);
                *(uint2*)(rp + w0) = q;
            }
        } else {
            float* rp0 = (float*)outv + ((size_t)(b * COUT + ca)  * H_ + h) * W_;
            float* rp1 = (float*)outv + ((size_t)(b * COUT + cb2) * H_ + h) * W_;
#pragma unroll
            for (int nt = 0; nt < 8; nt++) {
                int w0 = wn0 + nt * 8 + 2 * tig;
                float v0 = acc[mt][nt][0] * inva + bia;
                float v1 = acc[mt][nt][1] * inva + bia;
                float v2 = acc[mt][nt][2] * invb + bib;
                float v3 = acc[mt][nt][3] * invb + bib;
                if (RELU) { v0=fmaxf(v0,0.f); v1=fmaxf(v1,0.f); v2=fmaxf(v2,0.f); v3=fmaxf(v3,0.f); }
                *(float2*)(rp0 + w0) = make_float2(v0, v1);
                *(float2*)(rp1 + w0) = make_float2(v2, v3);
            }
        }
    }
}

// ---------------------------------------------------------------------------
// Prep: x NCHW fp32 -> [b][ci2][h][w] half2 (pair = 2ci2, 2ci2+1).
// ---------------------------------------------------------------------------
__global__ void xpose_h(const float* __restrict__ x, unsigned* __restrict__ xh)
{
    size_t idx = (size_t)blockIdx.x * 256 + threadIdx.x;   // B*128*H*W
    int w = idx & 127;
    int h = (idx >> 7) & 127;
    int ci2 = (idx >> 14) & 127;
    int b = idx >> 21;
    float x0 = x[(((size_t)b * CIN1 + 2 * ci2)     * H_ + h) * W_ + w];
    float x1 = x[(((size_t)b * CIN1 + 2 * ci2 + 1) * H_ + h) * W_ + w];
    xh[idx] = h2u(x0, x1);
}

// Prep: weights [co][ci][3][3] -> [chunk][tap][ci2][co] half2.
// PAIR8: pair j = (16*(j>>3)+(j&7), +8)  (matches conv epilogue pairing); else (2j, 2j+1).
template <int CIN, bool PAIR8>
__global__ void wpack_h(const float* __restrict__ w, unsigned* __restrict__ wo)
{
    int idx = blockIdx.x * 256 + threadIdx.x;     // (CIN/2)*9*128
    if (idx >= (CIN / 2) * 9 * 128) return;
    int co = idx & 127;
    int tap = (idx >> 7) % 9;
    int jg = idx / (9 * 128);
    int ca, cbb;
    if (PAIR8) { ca = (jg >> 3) * 16 + (jg & 7); cbb = ca + 8; }
    else       { ca = 2 * jg;                    cbb = ca + 1; }
    float wa = w[((size_t)co * CIN + ca)  * 9 + tap];
    float wb = w[((size_t)co * CIN + cbb) * 9 + tap];
    wo[((size_t)((jg >> 3) * 9 + tap)) * 1024 + (jg & 7) * 128 + co] = h2u(wa, wb);
}

// ---------------------------------------------------------------------------
// TopPool (reverse cummax over H) + add on half2 pair tensors.
// ---------------------------------------------------------------------------
__global__ void tpool_h(const unsigned* __restrict__ up, const unsigned* __restrict__ dn,
                        unsigned* __restrict__ mg)
{
    int idx = blockIdx.x * 256 + threadIdx.x;   // B*64*W
    int w = idx & 127;
    int bj = idx >> 7;
    size_t base = (size_t)bj * H_ * W_ + w;
    unsigned ru = 0xFC00FC00u;                  // half2(-inf,-inf)
    __half2 run = *(__half2*)&ru;
#pragma unroll 4
    for (int h = H_ - 1; h >= 0; h--) {
        size_t o = base + (size_t)h * W_;
        __half2 u = *(__half2*)&up[o];
        __half2 d = *(__half2*)&dn[o];
        run = __hmax2(run, u);
        __half2 m = __hadd2(run, d);
        mg[o] = *(unsigned*)&m;
    }
}

// ---------------------------------------------------------------------------
// LeftPool (reverse cummax over W), NCHW fp32, Hillis-Steele per row.
// ---------------------------------------------------------------------------
__global__ void leftpool(const float* __restrict__ in, float* __restrict__ out)
{
    __shared__ float s[W_];
    size_t base = (size_t)blockIdx.x * W_;
    int w = threadIdx.x;
    float v = in[base + w];
    s[w] = v; __syncthreads();
#pragma unroll
    for (int off = 1; off < W_; off <<= 1) {
        float o = (w + off < W_) ? s[w + off] : -INFINITY;
        __syncthreads();
        v = fmaxf(v, o); s[w] = v;
        __syncthreads();
    }
    out[base + w] = v;
}

// ---------------------------------------------------------------------------
extern "C" void kernel_launch(void* const* d_in, const int* in_sizes, int n_in,
                              void* d_out, int out_size)
{
    const float* x      = (const float*)d_in[0];
    const float* w_up   = (const float*)d_in[1];
    const float* up_g   = (const float*)d_in[2];
    const float* up_b   = (const float*)d_in[3];
    const float* up_m   = (const float*)d_in[4];
    const float* up_v   = (const float*)d_in[5];
    const float* w_down = (const float*)d_in[6];
    const float* dn_g   = (const float*)d_in[7];
    const float* dn_b   = (const float*)d_in[8];
    const float* dn_m   = (const float*)d_in[9];
    const float* dn_v   = (const float*)d_in[10];
    const float* w_p    = (const float*)d_in[11];
    const float* p_g    = (const float*)d_in[12];
    const float* p_b    = (const float*)d_in[13];
    const float* p_m    = (const float*)d_in[14];
    const float* p_v    = (const float*)d_in[15];
    float* outp = (float*)d_out;

    unsigned *xh, *uph, *dnh, *whu, *whd, *whp;
    cudaGetSymbolAddress((void**)&xh,  g_xh);
    cudaGetSymbolAddress((void**)&uph, g_uph);
    cudaGetSymbolAddress((void**)&dnh, g_dnh);
    cudaGetSymbolAddress((void**)&whu, g_whu);
    cudaGetSymbolAddress((void**)&whd, g_whd);
    cudaGetSymbolAddress((void**)&whp, g_whp);

    cudaFuncSetAttribute(conv_h<16, true,  true >, cudaFuncAttributeMaxDynamicSharedMemorySize, SMEM_BYTES);
    cudaFuncSetAttribute(conv_h< 8, false, false>, cudaFuncAttributeMaxDynamicSharedMemorySize, SMEM_BYTES);

    // prep
    {
        size_t n = (size_t)B_ * 128 * H_ * W_;
        xpose_h<<<(unsigned)(n / 256), 256>>>(x, xh);
        wpack_h<CIN1, false><<<(128 * 9 * 128 + 255) / 256, 256>>>(w_up,   whu);
        wpack_h<CIN1, false><<<(128 * 9 * 128 + 255) / 256, 256>>>(w_down, whd);
        wpack_h<COUT, true ><<<( 64 * 9 * 128 + 255) / 256, 256>>>(w_p,    whp);
    }

    dim3 cgrid(H_ / 2, B_);
    conv_h<16, true,  true ><<<cgrid, 256, SMEM_BYTES>>>(xh,  whu, up_g, up_b, up_m, up_v, uph);
    conv_h<16, true,  true ><<<cgrid, 256, SMEM_BYTES>>>(xh,  whd, dn_g, dn_b, dn_m, dn_v, dnh);
    tpool_h<<<(B_ * 64 * W_) / 256, 256>>>(uph, dnh, dnh);
    conv_h< 8, false, false><<<cgrid, 256, SMEM_BYTES>>>(dnh, whp, p_g, p_b, p_m, p_v, xh);
    leftpool<<<B_ * COUT * H_, W_>>>((const float*)xh, outp);
}